// round 2
// baseline (speedup 1.0000x reference)
#include <cuda_runtime.h>
#include <math.h>

#define BB 32
#define VV 16
#define LL 64
#define PP 64
#define DD 64
#define NTOK 32768      // BB*VV*LL
#define NQ 8
#define BINS 1024
#define EPSF 1e-5f
#define TPAD 65

#define ZQ_OFF   (NTOK*DD)           // 2097152
#define CODES_N  (NQ*NTOK)           // 262144

// ---------------- scratch (device globals; no allocation allowed) -------------
__device__ __align__(16) float  g_z[NTOK*DD];     // |FFT| per patch  [token][d]
__device__ __align__(16) float  g_zh[NTOK*DD];    // encoder output   [token][e]
__device__ float  g_cbsq[NQ*BINS];
__device__ double g_sum[LL], g_sumsq[LL];
__device__ float  g_mean[LL], g_sinv[LL], g_spe[LL];
__device__ double g_colnorm[BB*DD];
__device__ float  g_invnorm[BB*DD];
__device__ double g_loss[NQ];

// ---------------- k0: zero accumulators (graph replays!) ----------------------
__global__ void k_zero() {
    int t = threadIdx.x;
    if (t < LL) { g_sum[t] = 0.0; g_sumsq[t] = 0.0; }
    if (t < NQ) g_loss[t] = 0.0;
    for (int i = t; i < BB*DD; i += blockDim.x) g_colnorm[i] = 0.0;
}

// ---------------- k1: 64-pt DFT magnitude per patch ---------------------------
// grid = BB*LL blocks, 1024 threads (16 vars x 64 bins)
__global__ void __launch_bounds__(1024) k_fft(const float* __restrict__ x) {
    __shared__ float xs[PP*VV];       // [j][v], matches memory order of x[b][t][v]
    __shared__ float ct[64], st[64];
    int bi = blockIdx.x;
    int b = bi >> 6, l = bi & 63;
    int tid = threadIdx.x;
    xs[tid] = x[(size_t)(b*4096 + l*64)*16 + tid];
    if (tid < 64) { float a = (float)tid * (1.0f/32.0f); ct[tid] = cospif(a); st[tid] = sinpif(a); }
    __syncthreads();
    int v = tid >> 6, k = tid & 63;
    float re = 0.f, im = 0.f;
    #pragma unroll 16
    for (int j = 0; j < 64; j++) {
        float val = xs[j*16 + v];
        int a = (j*k) & 63;
        re += val * ct[a];
        im += val * st[a];
    }
    float mag = sqrtf(re*re + im*im);
    int t = (b*VV + v)*LL + l;
    g_z[t*64 + k] = mag;
}

// ---------------- k2: per-l sum / sumsq over (b,v,d) --------------------------
// grid = 512 (one per (b,v)), 256 threads
__global__ void k_stats() {
    int bv = blockIdx.x;
    const float* p = g_z + bv*4096;
    int tid = threadIdx.x;
    int l = tid >> 2, seg = (tid & 3)*16;
    const float* q = p + l*64 + seg;
    float s = 0.f, ss = 0.f;
    #pragma unroll
    for (int i = 0; i < 16; i++) { float v = q[i]; s += v; ss += v*v; }
    s  += __shfl_xor_sync(0xffffffffu, s, 1);  ss += __shfl_xor_sync(0xffffffffu, ss, 1);
    s  += __shfl_xor_sync(0xffffffffu, s, 2);  ss += __shfl_xor_sync(0xffffffffu, ss, 2);
    if ((tid & 3) == 0) {
        atomicAdd(&g_sum[l], (double)s);
        atomicAdd(&g_sumsq[l], (double)ss);
    }
}

// ---------------- k3: finalize mean / std (ddof=1) ----------------------------
__global__ void k_statfin() {
    int l = threadIdx.x;
    if (l >= LL) return;
    double n = 32768.0;
    double s = g_sum[l], ss = g_sumsq[l];
    double mean = s / n;
    double var = (ss - s*s/n) / (n - 1.0);
    float sd = (float)sqrt(var);
    g_mean[l] = (float)mean;
    float spe = sd + EPSF;
    g_spe[l] = spe;
    g_sinv[l] = 1.0f / spe;
}

// ---------------- k4: codebook squared norms ----------------------------------
// grid = 128, 256 threads -> 64 rows/block, 4 threads/row
__global__ void k_cbsq(const float* __restrict__ cb) {
    int tid = threadIdx.x;
    int row = blockIdx.x*64 + (tid >> 2);
    const float* p = cb + row*64 + (tid & 3)*16;
    float s = 0.f;
    #pragma unroll
    for (int i = 0; i < 16; i++) { float v = p[i]; s += v*v; }
    s += __shfl_xor_sync(0xffffffffu, s, 1);
    s += __shfl_xor_sync(0xffffffffu, s, 2);
    if ((tid & 3) == 0) g_cbsq[row] = s;
}

// ---------------- k5: encoder GEMM + per-(b,e) column norms -------------------
// grid = 256 (tiles of 128 tokens), 256 threads (16x16), each thread 8tok x 4e
__global__ void __launch_bounds__(256, 2) k_enc(const float* __restrict__ ew,
                                                const float* __restrict__ eb) {
    extern __shared__ float sm[];
    float* zS   = sm;               // 128*TPAD
    float* wS   = zS + 128*TPAD;    // 64*TPAD
    float* red  = wS + 64*TPAD;     // 64*17
    float* meanS= red + 64*17;      // 64
    float* sinvS= meanS + 64;       // 64
    float* ebS  = sinvS + 64;       // 64

    int tid = threadIdx.x;
    int t0 = blockIdx.x * 128;

    if (tid < 64) { meanS[tid] = g_mean[tid]; sinvS[tid] = g_sinv[tid]; ebS[tid] = eb[tid]; }
    {   // weights
        const float4* w4 = (const float4*)ew;
        #pragma unroll
        for (int i = 0; i < 4; i++) {
            int f = tid + i*256;
            int e = f >> 4, d4 = f & 15;
            float4 v = w4[f];
            float* dst = wS + e*TPAD + d4*4;
            dst[0]=v.x; dst[1]=v.y; dst[2]=v.z; dst[3]=v.w;
        }
    }
    __syncthreads();
    {   // z tile, normalized on load (per-l scalar)
        const float4* z4 = (const float4*)g_z + (size_t)t0*16;
        #pragma unroll
        for (int i = 0; i < 8; i++) {
            int f = tid + i*256;
            int t = f >> 4, d4 = f & 15;
            float4 v = z4[f];
            int l = (t0 + t) & 63;
            float m = meanS[l], si = sinvS[l];
            float* dst = zS + t*TPAD + d4*4;
            dst[0]=(v.x-m)*si; dst[1]=(v.y-m)*si; dst[2]=(v.z-m)*si; dst[3]=(v.w-m)*si;
        }
    }
    __syncthreads();

    int ty = tid >> 4, tx = tid & 15;
    float acc[8][4];
    #pragma unroll
    for (int i = 0; i < 8; i++)
        #pragma unroll
        for (int j = 0; j < 4; j++) acc[i][j] = 0.f;

    #pragma unroll 16
    for (int d = 0; d < 64; d++) {
        float rv[8], cv[4];
        #pragma unroll
        for (int i = 0; i < 8; i++) rv[i] = zS[(ty*8+i)*TPAD + d];
        #pragma unroll
        for (int j = 0; j < 4; j++) cv[j] = wS[(tx*4+j)*TPAD + d];
        #pragma unroll
        for (int i = 0; i < 8; i++)
            #pragma unroll
            for (int j = 0; j < 4; j++) acc[i][j] += rv[i]*cv[j];
    }

    float pn[4] = {0.f,0.f,0.f,0.f};
    #pragma unroll
    for (int i = 0; i < 8; i++) {
        int t = t0 + ty*8 + i;
        float4 o;
        o.x = acc[i][0] + ebS[tx*4+0];
        o.y = acc[i][1] + ebS[tx*4+1];
        o.z = acc[i][2] + ebS[tx*4+2];
        o.w = acc[i][3] + ebS[tx*4+3];
        pn[0] += o.x*o.x; pn[1] += o.y*o.y; pn[2] += o.z*o.z; pn[3] += o.w*o.w;
        ((float4*)g_zh)[(size_t)t*16 + tx] = o;
    }
    #pragma unroll
    for (int j = 0; j < 4; j++) red[(tx*4+j)*17 + ty] = pn[j];
    __syncthreads();
    if (tid < 64) {
        float s = 0.f;
        #pragma unroll
        for (int y = 0; y < 16; y++) s += red[tid*17 + y];
        atomicAdd(&g_colnorm[(t0 >> 10)*64 + tid], (double)s);
    }
}

// ---------------- k6: finalize inverse token-norms ----------------------------
__global__ void k_normfin() {
    int i = blockIdx.x*blockDim.x + threadIdx.x;
    if (i < BB*DD) g_invnorm[i] = 1.0f / sqrtf((float)g_colnorm[i]);
}

// ---------------- k7: RVQ (8 stages) + fused decoder --------------------------
// grid = 256 (128 tokens each), 256 threads (16x16), thread = 8 tok x 4 entries
__global__ void __launch_bounds__(256, 2) k_rvq(const float* __restrict__ cb,
                                                const float* __restrict__ dw,
                                                const float* __restrict__ db,
                                                float* __restrict__ out) {
    extern __shared__ float sm[];
    float* resS  = sm;                  // 128*TPAD
    float* qoS   = resS + 128*TPAD;     // 128*TPAD
    float* cbS   = qoS  + 128*TPAD;     // 64*TPAD (reused for dec_w)
    float* csqS  = cbS  + 64*TPAD;      // 64
    float* invS  = csqS + 64;           // 64
    float* meanS = invS + 64;           // 64
    float* speS  = meanS + 64;          // 64
    float* dbS   = speS + 64;           // 64
    float* redD  = dbS  + 64;           // 128*17
    int*   redI  = (int*)(redD + 128*17); // 128*17
    int*   idxS  = redI + 128*17;       // 128

    int tid = threadIdx.x;
    int t0 = blockIdx.x * 128;
    int b = t0 >> 10;

    if (tid < 64) {
        invS[tid]  = g_invnorm[b*64 + tid];
        meanS[tid] = g_mean[tid];
        speS[tid]  = g_spe[tid];
        dbS[tid]   = db[tid];
    }
    __syncthreads();
    {   // load residual = z_h * invnorm ; zero qo
        const float4* zh4 = (const float4*)g_zh + (size_t)t0*16;
        #pragma unroll
        for (int i = 0; i < 8; i++) {
            int f = tid + i*256;
            int t = f >> 4, e4 = f & 15;
            float4 v = zh4[f];
            float* dst = resS + t*TPAD + e4*4;
            float* qd  = qoS  + t*TPAD + e4*4;
            dst[0] = v.x * invS[e4*4+0];
            dst[1] = v.y * invS[e4*4+1];
            dst[2] = v.z * invS[e4*4+2];
            dst[3] = v.w * invS[e4*4+3];
            qd[0]=0.f; qd[1]=0.f; qd[2]=0.f; qd[3]=0.f;
        }
    }
    __syncthreads();

    int ty = tid >> 4, tx = tid & 15;

    for (int q = 0; q < NQ; q++) {
        float best[8]; int bidx[8];
        #pragma unroll
        for (int i = 0; i < 8; i++) { best[i] = INFINITY; bidx[i] = 0; }

        for (int ch = 0; ch < 16; ch++) {
            {   // stream 64-entry codebook chunk
                const float4* c4 = (const float4*)cb + (size_t)(q*BINS + ch*64)*16;
                #pragma unroll
                for (int i = 0; i < 4; i++) {
                    int f = tid + i*256;
                    int e = f >> 4, d4 = f & 15;
                    float4 v = c4[f];
                    float* dst = cbS + e*TPAD + d4*4;
                    dst[0]=v.x; dst[1]=v.y; dst[2]=v.z; dst[3]=v.w;
                }
                if (tid < 64) csqS[tid] = g_cbsq[q*BINS + ch*64 + tid];
            }
            __syncthreads();

            float acc[8][4];
            #pragma unroll
            for (int i = 0; i < 8; i++)
                #pragma unroll
                for (int j = 0; j < 4; j++) acc[i][j] = 0.f;

            #pragma unroll 16
            for (int d = 0; d < 64; d++) {
                float rv[8], cv[4];
                #pragma unroll
                for (int i = 0; i < 8; i++) rv[i] = resS[(ty*8+i)*TPAD + d];
                #pragma unroll
                for (int j = 0; j < 4; j++) cv[j] = cbS[(tx*4+j)*TPAD + d];
                #pragma unroll
                for (int i = 0; i < 8; i++)
                    #pragma unroll
                    for (int j = 0; j < 4; j++) acc[i][j] += rv[i]*cv[j];
            }
            // argmin uses m = ||c||^2 - 2 r.c  (||r||^2 constant over entries)
            #pragma unroll
            for (int j = 0; j < 4; j++) {
                float cq = csqS[tx*4 + j];
                int gi = ch*64 + tx*4 + j;
                #pragma unroll
                for (int i = 0; i < 8; i++) {
                    float m = cq - 2.0f*acc[i][j];
                    if (m < best[i]) { best[i] = m; bidx[i] = gi; }
                }
            }
            __syncthreads();   // cbS/csqS reused next chunk
        }

        // cross-thread argmin over the 16 entry-groups
        #pragma unroll
        for (int i = 0; i < 8; i++) {
            redD[(ty*8+i)*17 + tx] = best[i];
            redI[(ty*8+i)*17 + tx] = bidx[i];
        }
        __syncthreads();
        if (tid < 128) {
            float bd = INFINITY; int bi = 0x7fffffff;
            #pragma unroll
            for (int k = 0; k < 16; k++) {
                float d = redD[tid*17 + k]; int ii = redI[tid*17 + k];
                if (d < bd || (d == bd && ii < bi)) { bd = d; bi = ii; }
            }
            idxS[tid] = bi;
            out[ZQ_OFF + q*NTOK + t0 + tid] = (float)bi;   // codes as float
        }
        __syncthreads();

        // update residual & accumulated quantize; loss = mean(new_residual^2)
        float ls = 0.f;
        {
            int t = tid >> 1;
            int dbase = (tid & 1)*32;
            const float* crow = cb + (size_t)(q*BINS + idxS[t])*64 + dbase;
            #pragma unroll
            for (int jj = 0; jj < 32; jj++) {
                float c = crow[jj];
                int d = dbase + jj;
                float nv = resS[t*TPAD + d] - c;
                resS[t*TPAD + d] = nv;
                qoS[t*TPAD + d] += c;
                ls += nv*nv;
            }
        }
        #pragma unroll
        for (int o = 16; o; o >>= 1) ls += __shfl_xor_sync(0xffffffffu, ls, o);
        __syncthreads();           // argmin scratch consumed; reuse redD
        if ((tid & 31) == 0) redD[tid >> 5] = ls;
        __syncthreads();
        if (tid == 0) {
            float s = 0.f;
            #pragma unroll
            for (int w = 0; w < 8; w++) s += redD[w];
            atomicAdd(&g_loss[q], (double)s);
        }
        __syncthreads();
    }

    // -------- fused decoder: out = (qo @ dec_w^T + db) * spe[l] + mean[l] -----
    {   // dec_w into cbS
        const float4* w4 = (const float4*)dw;
        #pragma unroll
        for (int i = 0; i < 4; i++) {
            int f = tid + i*256;
            int e = f >> 4, d4 = f & 15;
            float4 v = w4[f];
            float* dst = cbS + e*TPAD + d4*4;
            dst[0]=v.x; dst[1]=v.y; dst[2]=v.z; dst[3]=v.w;
        }
    }
    __syncthreads();
    float acc[8][4];
    #pragma unroll
    for (int i = 0; i < 8; i++)
        #pragma unroll
        for (int j = 0; j < 4; j++) acc[i][j] = 0.f;
    #pragma unroll 16
    for (int d = 0; d < 64; d++) {
        float rv[8], cv[4];
        #pragma unroll
        for (int i = 0; i < 8; i++) rv[i] = qoS[(ty*8+i)*TPAD + d];
        #pragma unroll
        for (int j = 0; j < 4; j++) cv[j] = cbS[(tx*4+j)*TPAD + d];
        #pragma unroll
        for (int i = 0; i < 8; i++)
            #pragma unroll
            for (int j = 0; j < 4; j++) acc[i][j] += rv[i]*cv[j];
    }
    #pragma unroll
    for (int i = 0; i < 8; i++) {
        int t = t0 + ty*8 + i;
        int l = t & 63;
        float sp = speS[l], mm = meanS[l];
        float4 o;
        o.x = (acc[i][0] + dbS[tx*4+0])*sp + mm;
        o.y = (acc[i][1] + dbS[tx*4+1])*sp + mm;
        o.z = (acc[i][2] + dbS[tx*4+2])*sp + mm;
        o.w = (acc[i][3] + dbS[tx*4+3])*sp + mm;
        ((float4*)out)[(size_t)t*16 + tx] = o;
    }
}

// ---------------- k8: commit loss ---------------------------------------------
__global__ void k_lossfin(float* __restrict__ out) {
    if (threadIdx.x == 0 && blockIdx.x == 0) {
        double s = 0.0;
        for (int q = 0; q < NQ; q++) s += g_loss[q] / (double)(NTOK*DD);
        out[ZQ_OFF + CODES_N] = (float)(s / (double)NQ);
    }
}

// ---------------- launch ------------------------------------------------------
extern "C" void kernel_launch(void* const* d_in, const int* in_sizes, int n_in,
                              void* d_out, int out_size) {
    const float* x    = (const float*)d_in[0];
    const float* ew   = (const float*)d_in[1];
    const float* eb   = (const float*)d_in[2];
    const float* dwp  = (const float*)d_in[3];
    const float* dbp  = (const float*)d_in[4];
    const float* cb   = (const float*)d_in[5];
    float* out = (float*)d_out;

    // Idempotent, called every launch (no static guards per harness rules).
    // Not a stream-ordered op, so legal under graph capture.
    const int ENC_SMEM = (128*TPAD + 64*TPAD + 64*17 + 3*64) * 4;
    const int RVQ_SMEM = (128*TPAD*2 + 64*TPAD + 64 + 4*64 + 128*17*2 + 128) * 4;
    cudaFuncSetAttribute(k_enc, cudaFuncAttributeMaxDynamicSharedMemorySize, ENC_SMEM);
    cudaFuncSetAttribute(k_rvq, cudaFuncAttributeMaxDynamicSharedMemorySize, RVQ_SMEM);

    k_zero<<<1, 256>>>();
    k_fft<<<BB*LL, 1024>>>(x);
    k_stats<<<512, 256>>>();
    k_statfin<<<1, 64>>>();
    k_cbsq<<<128, 256>>>(cb);
    k_enc<<<256, 256, ENC_SMEM>>>(ew, eb);
    k_normfin<<<8, 256>>>();
    k_rvq<<<256, 256, RVQ_SMEM>>>(cb, dwp, dbp, out);
    k_lossfin<<<1, 32>>>(out);
}

// round 3
// speedup vs baseline: 1.0098x; 1.0098x over previous
#include <cuda_runtime.h>
#include <math.h>

#define BB 32
#define VV 16
#define LL 64
#define PP 64
#define DD 64
#define NTOK 32768      // BB*VV*LL
#define NQ 8
#define BINS 1024
#define EPSF 1e-5f
#define TPAD 66         // even -> 8B-aligned ld.shared.b64 at even d

#define ZQ_OFF   (NTOK*DD)           // 2097152
#define CODES_N  (NQ*NTOK)           // 262144

typedef unsigned long long ull;

// packed fp32x2 fma: acc = a*b + acc (two independent fp32 lanes)
__device__ __forceinline__ void fma2(ull& acc, ull a, ull b) {
    asm("fma.rn.f32x2 %0, %1, %2, %0;" : "+l"(acc) : "l"(a), "l"(b));
}
__device__ __forceinline__ float unpack_sum(ull a) {
    float2 p = *reinterpret_cast<float2*>(&a);
    return p.x + p.y;
}

// ---------------- scratch (device globals; no allocation allowed) -------------
__device__ __align__(16) float  g_z[NTOK*DD];     // |FFT| per patch  [token][d]
__device__ __align__(16) float  g_zh[NTOK*DD];    // encoder output   [token][e]
__device__ float  g_cbsq[NQ*BINS];
__device__ double g_sum[LL], g_sumsq[LL];
__device__ float  g_mean[LL], g_sinv[LL], g_spe[LL];
__device__ double g_colnorm[BB*DD];
__device__ float  g_invnorm[BB*DD];
__device__ double g_loss[NQ];

// ---------------- k0: zero accumulators (graph replays!) ----------------------
__global__ void k_zero() {
    int t = threadIdx.x;
    if (t < LL) { g_sum[t] = 0.0; g_sumsq[t] = 0.0; }
    if (t < NQ) g_loss[t] = 0.0;
    for (int i = t; i < BB*DD; i += blockDim.x) g_colnorm[i] = 0.0;
}

// ---------------- k1: 64-pt DFT magnitude per patch ---------------------------
// grid = BB*LL blocks, 1024 threads (16 vars x 64 bins)
__global__ void __launch_bounds__(1024) k_fft(const float* __restrict__ x) {
    __shared__ float xs[PP*VV];       // [j][v], matches memory order of x[b][t][v]
    __shared__ float ct[64], st[64];
    int bi = blockIdx.x;
    int b = bi >> 6, l = bi & 63;
    int tid = threadIdx.x;
    xs[tid] = x[(size_t)(b*4096 + l*64)*16 + tid];
    if (tid < 64) { float a = (float)tid * (1.0f/32.0f); ct[tid] = cospif(a); st[tid] = sinpif(a); }
    __syncthreads();
    int v = tid >> 6, k = tid & 63;
    float re = 0.f, im = 0.f;
    #pragma unroll 16
    for (int j = 0; j < 64; j++) {
        float val = xs[j*16 + v];
        int a = (j*k) & 63;
        re += val * ct[a];
        im += val * st[a];
    }
    float mag = sqrtf(re*re + im*im);
    int t = (b*VV + v)*LL + l;
    g_z[t*64 + k] = mag;
}

// ---------------- k2: per-l sum / sumsq over (b,v,d) --------------------------
__global__ void k_stats() {
    int bv = blockIdx.x;
    const float* p = g_z + bv*4096;
    int tid = threadIdx.x;
    int l = tid >> 2, seg = (tid & 3)*16;
    const float* q = p + l*64 + seg;
    float s = 0.f, ss = 0.f;
    #pragma unroll
    for (int i = 0; i < 16; i++) { float v = q[i]; s += v; ss += v*v; }
    s  += __shfl_xor_sync(0xffffffffu, s, 1);  ss += __shfl_xor_sync(0xffffffffu, ss, 1);
    s  += __shfl_xor_sync(0xffffffffu, s, 2);  ss += __shfl_xor_sync(0xffffffffu, ss, 2);
    if ((tid & 3) == 0) {
        atomicAdd(&g_sum[l], (double)s);
        atomicAdd(&g_sumsq[l], (double)ss);
    }
}

// ---------------- k3: finalize mean / std (ddof=1) ----------------------------
__global__ void k_statfin() {
    int l = threadIdx.x;
    if (l >= LL) return;
    double n = 32768.0;
    double s = g_sum[l], ss = g_sumsq[l];
    double mean = s / n;
    double var = (ss - s*s/n) / (n - 1.0);
    float sd = (float)sqrt(var);
    g_mean[l] = (float)mean;
    float spe = sd + EPSF;
    g_spe[l] = spe;
    g_sinv[l] = 1.0f / spe;
}

// ---------------- k4: codebook squared norms ----------------------------------
__global__ void k_cbsq(const float* __restrict__ cb) {
    int tid = threadIdx.x;
    int row = blockIdx.x*64 + (tid >> 2);
    const float* p = cb + row*64 + (tid & 3)*16;
    float s = 0.f;
    #pragma unroll
    for (int i = 0; i < 16; i++) { float v = p[i]; s += v*v; }
    s += __shfl_xor_sync(0xffffffffu, s, 1);
    s += __shfl_xor_sync(0xffffffffu, s, 2);
    if ((tid & 3) == 0) g_cbsq[row] = s;
}

// ---------------- k5: encoder GEMM + per-(b,e) column norms -------------------
// grid = 256 (tiles of 128 tokens), 256 threads (16x16), thread: 8 tok x 4 cols
// column assignment e = j*16 + tx (strided -> conflict-free b64 smem loads)
__global__ void __launch_bounds__(256, 2) k_enc(const float* __restrict__ ew,
                                                const float* __restrict__ eb) {
    extern __shared__ float sm[];
    float* zS   = sm;               // 128*TPAD
    float* wS   = zS + 128*TPAD;    // 64*TPAD
    float* red  = wS + 64*TPAD;     // 64*17
    float* meanS= red + 64*17;      // 64
    float* sinvS= meanS + 64;       // 64
    float* ebS  = sinvS + 64;       // 64

    int tid = threadIdx.x;
    int t0 = blockIdx.x * 128;

    if (tid < 64) { meanS[tid] = g_mean[tid]; sinvS[tid] = g_sinv[tid]; ebS[tid] = eb[tid]; }
    {   // weights
        const float4* w4 = (const float4*)ew;
        #pragma unroll
        for (int i = 0; i < 4; i++) {
            int f = tid + i*256;
            int e = f >> 4, d4 = f & 15;
            float4 v = w4[f];
            float* dst = wS + e*TPAD + d4*4;
            dst[0]=v.x; dst[1]=v.y; dst[2]=v.z; dst[3]=v.w;
        }
    }
    __syncthreads();
    {   // z tile, normalized on load (per-l scalar)
        const float4* z4 = (const float4*)g_z + (size_t)t0*16;
        #pragma unroll
        for (int i = 0; i < 8; i++) {
            int f = tid + i*256;
            int t = f >> 4, d4 = f & 15;
            float4 v = z4[f];
            int l = (t0 + t) & 63;
            float m = meanS[l], si = sinvS[l];
            float* dst = zS + t*TPAD + d4*4;
            dst[0]=(v.x-m)*si; dst[1]=(v.y-m)*si; dst[2]=(v.z-m)*si; dst[3]=(v.w-m)*si;
        }
    }
    __syncthreads();

    int ty = tid >> 4, tx = tid & 15;
    ull acc2[8][4];
    #pragma unroll
    for (int i = 0; i < 8; i++)
        #pragma unroll
        for (int j = 0; j < 4; j++) acc2[i][j] = 0ull;

    #pragma unroll 8
    for (int d = 0; d < 64; d += 2) {
        ull rv[8], cv[4];
        #pragma unroll
        for (int i = 0; i < 8; i++) rv[i] = *(const ull*)(zS + (ty*8+i)*TPAD + d);
        #pragma unroll
        for (int j = 0; j < 4; j++) cv[j] = *(const ull*)(wS + (j*16+tx)*TPAD + d);
        #pragma unroll
        for (int i = 0; i < 8; i++)
            #pragma unroll
            for (int j = 0; j < 4; j++) fma2(acc2[i][j], rv[i], cv[j]);
    }

    float pn[4] = {0.f,0.f,0.f,0.f};
    #pragma unroll
    for (int i = 0; i < 8; i++) {
        int t = t0 + ty*8 + i;
        #pragma unroll
        for (int j = 0; j < 4; j++) {
            int e = j*16 + tx;
            float o = unpack_sum(acc2[i][j]) + ebS[e];
            pn[j] += o*o;
            g_zh[(size_t)t*64 + e] = o;
        }
    }
    #pragma unroll
    for (int j = 0; j < 4; j++) red[(j*16+tx)*17 + ty] = pn[j];
    __syncthreads();
    if (tid < 64) {
        float s = 0.f;
        #pragma unroll
        for (int y = 0; y < 16; y++) s += red[tid*17 + y];
        atomicAdd(&g_colnorm[(t0 >> 10)*64 + tid], (double)s);
    }
}

// ---------------- k6: finalize inverse token-norms ----------------------------
__global__ void k_normfin() {
    int i = blockIdx.x*blockDim.x + threadIdx.x;
    if (i < BB*DD) g_invnorm[i] = 1.0f / sqrtf((float)g_colnorm[i]);
}

// ---------------- k7: RVQ (8 stages) + fused decoder --------------------------
// grid = 256 (128 tokens each), 256 threads (16x16), thread = 8 tok x 4 entries
// entry assignment e = j*16 + tx (strided)
__global__ void __launch_bounds__(256, 2) k_rvq(const float* __restrict__ cb,
                                                const float* __restrict__ dw,
                                                const float* __restrict__ db,
                                                float* __restrict__ out) {
    extern __shared__ float sm[];
    float* resS  = sm;                  // 128*TPAD
    float* qoS   = resS + 128*TPAD;     // 128*TPAD
    float* cbS   = qoS  + 128*TPAD;     // 64*TPAD (reused for dec_w)
    float* csqS  = cbS  + 64*TPAD;      // 64
    float* invS  = csqS + 64;           // 64
    float* meanS = invS + 64;           // 64
    float* speS  = meanS + 64;          // 64
    float* dbS   = speS + 64;           // 64
    float* redD  = dbS  + 64;           // 128*17
    int*   redI  = (int*)(redD + 128*17); // 128*17
    int*   idxS  = redI + 128*17;       // 128

    int tid = threadIdx.x;
    int t0 = blockIdx.x * 128;
    int b = t0 >> 10;

    if (tid < 64) {
        invS[tid]  = g_invnorm[b*64 + tid];
        meanS[tid] = g_mean[tid];
        speS[tid]  = g_spe[tid];
        dbS[tid]   = db[tid];
    }
    __syncthreads();
    {   // load residual = z_h * invnorm ; zero qo
        const float4* zh4 = (const float4*)g_zh + (size_t)t0*16;
        #pragma unroll
        for (int i = 0; i < 8; i++) {
            int f = tid + i*256;
            int t = f >> 4, e4 = f & 15;
            float4 v = zh4[f];
            float* dst = resS + t*TPAD + e4*4;
            float* qd  = qoS  + t*TPAD + e4*4;
            dst[0] = v.x * invS[e4*4+0];
            dst[1] = v.y * invS[e4*4+1];
            dst[2] = v.z * invS[e4*4+2];
            dst[3] = v.w * invS[e4*4+3];
            qd[0]=0.f; qd[1]=0.f; qd[2]=0.f; qd[3]=0.f;
        }
    }
    __syncthreads();

    int ty = tid >> 4, tx = tid & 15;

    for (int q = 0; q < NQ; q++) {
        float best[8]; int bidx[8];
        #pragma unroll
        for (int i = 0; i < 8; i++) { best[i] = INFINITY; bidx[i] = 0; }

        for (int ch = 0; ch < 16; ch++) {
            {   // stream 64-entry codebook chunk
                const float4* c4 = (const float4*)cb + (size_t)(q*BINS + ch*64)*16;
                #pragma unroll
                for (int i = 0; i < 4; i++) {
                    int f = tid + i*256;
                    int e = f >> 4, d4 = f & 15;
                    float4 v = c4[f];
                    float* dst = cbS + e*TPAD + d4*4;
                    dst[0]=v.x; dst[1]=v.y; dst[2]=v.z; dst[3]=v.w;
                }
                if (tid < 64) csqS[tid] = g_cbsq[q*BINS + ch*64 + tid];
            }
            __syncthreads();

            ull acc2[8][4];
            #pragma unroll
            for (int i = 0; i < 8; i++)
                #pragma unroll
                for (int j = 0; j < 4; j++) acc2[i][j] = 0ull;

            #pragma unroll 8
            for (int d = 0; d < 64; d += 2) {
                ull rv[8], cv[4];
                #pragma unroll
                for (int i = 0; i < 8; i++) rv[i] = *(const ull*)(resS + (ty*8+i)*TPAD + d);
                #pragma unroll
                for (int j = 0; j < 4; j++) cv[j] = *(const ull*)(cbS + (j*16+tx)*TPAD + d);
                #pragma unroll
                for (int i = 0; i < 8; i++)
                    #pragma unroll
                    for (int j = 0; j < 4; j++) fma2(acc2[i][j], rv[i], cv[j]);
            }
            // argmin metric m = ||c||^2 - 2 r.c  (||r||^2 constant over entries)
            #pragma unroll
            for (int j = 0; j < 4; j++) {
                int e = j*16 + tx;
                float cq = csqS[e];
                int gi = ch*64 + e;
                #pragma unroll
                for (int i = 0; i < 8; i++) {
                    float m = cq - 2.0f*unpack_sum(acc2[i][j]);
                    if (m < best[i]) { best[i] = m; bidx[i] = gi; }
                }
            }
            __syncthreads();   // cbS/csqS reused next chunk
        }

        // cross-thread argmin over the 16 entry-groups
        #pragma unroll
        for (int i = 0; i < 8; i++) {
            redD[(ty*8+i)*17 + tx] = best[i];
            redI[(ty*8+i)*17 + tx] = bidx[i];
        }
        __syncthreads();
        if (tid < 128) {
            float bd = INFINITY; int bi = 0x7fffffff;
            #pragma unroll
            for (int k = 0; k < 16; k++) {
                float d = redD[tid*17 + k]; int ii = redI[tid*17 + k];
                if (d < bd || (d == bd && ii < bi)) { bd = d; bi = ii; }
            }
            idxS[tid] = bi;
            out[ZQ_OFF + q*NTOK + t0 + tid] = (float)bi;   // codes as float
        }
        __syncthreads();

        // update residual & accumulated quantize; loss = mean(new_residual^2)
        float ls = 0.f;
        {
            int t = tid >> 1;
            int dbase = (tid & 1)*32;
            const float* crow = cb + (size_t)(q*BINS + idxS[t])*64 + dbase;
            #pragma unroll
            for (int jj = 0; jj < 32; jj++) {
                float c = crow[jj];
                int d = dbase + jj;
                float nv = resS[t*TPAD + d] - c;
                resS[t*TPAD + d] = nv;
                qoS[t*TPAD + d] += c;
                ls += nv*nv;
            }
        }
        #pragma unroll
        for (int o = 16; o; o >>= 1) ls += __shfl_xor_sync(0xffffffffu, ls, o);
        __syncthreads();           // argmin scratch consumed; reuse redD
        if ((tid & 31) == 0) redD[tid >> 5] = ls;
        __syncthreads();
        if (tid == 0) {
            float s = 0.f;
            #pragma unroll
            for (int w = 0; w < 8; w++) s += redD[w];
            atomicAdd(&g_loss[q], (double)s);
        }
        __syncthreads();
    }

    // -------- fused decoder: out = (qo @ dec_w^T + db) * spe[l] + mean[l] -----
    {   // dec_w into cbS
        const float4* w4 = (const float4*)dw;
        #pragma unroll
        for (int i = 0; i < 4; i++) {
            int f = tid + i*256;
            int e = f >> 4, d4 = f & 15;
            float4 v = w4[f];
            float* dst = cbS + e*TPAD + d4*4;
            dst[0]=v.x; dst[1]=v.y; dst[2]=v.z; dst[3]=v.w;
        }
    }
    __syncthreads();
    ull acc2[8][4];
    #pragma unroll
    for (int i = 0; i < 8; i++)
        #pragma unroll
        for (int j = 0; j < 4; j++) acc2[i][j] = 0ull;
    #pragma unroll 8
    for (int d = 0; d < 64; d += 2) {
        ull rv[8], cv[4];
        #pragma unroll
        for (int i = 0; i < 8; i++) rv[i] = *(const ull*)(qoS + (ty*8+i)*TPAD + d);
        #pragma unroll
        for (int j = 0; j < 4; j++) cv[j] = *(const ull*)(cbS + (j*16+tx)*TPAD + d);
        #pragma unroll
        for (int i = 0; i < 8; i++)
            #pragma unroll
            for (int j = 0; j < 4; j++) fma2(acc2[i][j], rv[i], cv[j]);
    }
    #pragma unroll
    for (int i = 0; i < 8; i++) {
        int t = t0 + ty*8 + i;
        int l = t & 63;
        float sp = speS[l], mm = meanS[l];
        #pragma unroll
        for (int j = 0; j < 4; j++) {
            int e = j*16 + tx;
            out[(size_t)t*64 + e] = (unpack_sum(acc2[i][j]) + dbS[e])*sp + mm;
        }
    }
}

// ---------------- k8: commit loss ---------------------------------------------
__global__ void k_lossfin(float* __restrict__ out) {
    if (threadIdx.x == 0 && blockIdx.x == 0) {
        double s = 0.0;
        for (int q = 0; q < NQ; q++) s += g_loss[q] / (double)(NTOK*DD);
        out[ZQ_OFF + CODES_N] = (float)(s / (double)NQ);
    }
}

// ---------------- launch ------------------------------------------------------
extern "C" void kernel_launch(void* const* d_in, const int* in_sizes, int n_in,
                              void* d_out, int out_size) {
    const float* x    = (const float*)d_in[0];
    const float* ew   = (const float*)d_in[1];
    const float* eb   = (const float*)d_in[2];
    const float* dwp  = (const float*)d_in[3];
    const float* dbp  = (const float*)d_in[4];
    const float* cb   = (const float*)d_in[5];
    float* out = (float*)d_out;

    // Idempotent, called every launch (no static guards per harness rules).
    const int ENC_SMEM = (128*TPAD + 64*TPAD + 64*17 + 3*64) * 4;
    const int RVQ_SMEM = (128*TPAD*2 + 64*TPAD + 64 + 4*64 + 128*17*2 + 128) * 4;
    cudaFuncSetAttribute(k_enc, cudaFuncAttributeMaxDynamicSharedMemorySize, ENC_SMEM);
    cudaFuncSetAttribute(k_rvq, cudaFuncAttributeMaxDynamicSharedMemorySize, RVQ_SMEM);

    k_zero<<<1, 256>>>();
    k_fft<<<BB*LL, 1024>>>(x);
    k_stats<<<512, 256>>>();
    k_statfin<<<1, 64>>>();
    k_cbsq<<<128, 256>>>(cb);
    k_enc<<<256, 256, ENC_SMEM>>>(ew, eb);
    k_normfin<<<8, 256>>>();
    k_rvq<<<256, 256, RVQ_SMEM>>>(cb, dwp, dbp, out);
    k_lossfin<<<1, 32>>>(out);
}

// round 6
// speedup vs baseline: 1.4987x; 1.4842x over previous
#include <cuda_runtime.h>
#include <math.h>
#include <stdint.h>

#define BB 32
#define VV 16
#define LL 64
#define PP 64
#define DD 64
#define NTOK 32768      // BB*VV*LL
#define NQ 8
#define BINS 1024
#define EPSF 1e-5f
#define TPAD 66

#define ZQ_OFF   (NTOK*DD)           // 2097152
#define CODES_N  (NQ*NTOK)           // 262144

typedef unsigned long long ull;

__device__ __forceinline__ uint32_t f2tf32(float x) {
    uint32_t r; asm("cvt.rna.tf32.f32 %0, %1;" : "=r"(r) : "f"(x)); return r;
}

// m16n8k8 tf32 mma: D = A*B + D (fp32 accum). compute_80+ -> legal on compute_100.
__device__ __forceinline__ void mma_tf32(float* c, const uint32_t* a,
                                         uint32_t b0, uint32_t b1) {
    asm volatile("mma.sync.aligned.m16n8k8.row.col.f32.tf32.tf32.f32 "
        "{%0,%1,%2,%3}, {%4,%5,%6,%7}, {%8,%9}, {%0,%1,%2,%3};"
        : "+f"(c[0]), "+f"(c[1]), "+f"(c[2]), "+f"(c[3])
        : "r"(a[0]), "r"(a[1]), "r"(a[2]), "r"(a[3]), "r"(b0), "r"(b1));
}

// fp32x2 helpers for k_enc (lowered to 2x FFMA on sm_100; harmless)
__device__ __forceinline__ void fma2(ull& acc, ull a, ull b) {
    asm("fma.rn.f32x2 %0, %1, %2, %0;" : "+l"(acc) : "l"(a), "l"(b));
}
__device__ __forceinline__ float unpack_sum(ull a) {
    float2 p = *reinterpret_cast<float2*>(&a);
    return p.x + p.y;
}

// ---------------- scratch (device globals; no allocation allowed) -------------
__device__ __align__(16) float  g_z[NTOK*DD];
__device__ __align__(16) float  g_zh[NTOK*DD];
// pre-fragmented codebook for mma: [q][ch(16)][nt(8)][s(8)][lane(32)]{bhi0,bhi1,blo0,blo1}
__device__ __align__(16) float4 g_cbfrag[NQ*16*8*8*32];
__device__ float  g_cbsq[NQ*BINS];
__device__ double g_sum[LL], g_sumsq[LL];
__device__ float  g_mean[LL], g_sinv[LL], g_spe[LL];
__device__ double g_colnorm[BB*DD];
__device__ float  g_invnorm[BB*DD];
__device__ double g_loss[NQ];

// ---------------- k0: zero accumulators ---------------------------------------
__global__ void k_zero() {
    int t = threadIdx.x;
    if (t < LL) { g_sum[t] = 0.0; g_sumsq[t] = 0.0; }
    if (t < NQ) g_loss[t] = 0.0;
    for (int i = t; i < BB*DD; i += blockDim.x) g_colnorm[i] = 0.0;
}

// ---------------- k1: 64-pt DFT magnitude per patch ---------------------------
__global__ void __launch_bounds__(1024) k_fft(const float* __restrict__ x) {
    __shared__ float xs[PP*VV];
    __shared__ float ct[64], st[64];
    int bi = blockIdx.x;
    int b = bi >> 6, l = bi & 63;
    int tid = threadIdx.x;
    xs[tid] = x[(size_t)(b*4096 + l*64)*16 + tid];
    if (tid < 64) { float a = (float)tid * (1.0f/32.0f); ct[tid] = cospif(a); st[tid] = sinpif(a); }
    __syncthreads();
    int v = tid >> 6, k = tid & 63;
    float re = 0.f, im = 0.f;
    #pragma unroll 16
    for (int j = 0; j < 64; j++) {
        float val = xs[j*16 + v];
        int a = (j*k) & 63;
        re += val * ct[a];
        im += val * st[a];
    }
    float mag = sqrtf(re*re + im*im);
    int t = (b*VV + v)*LL + l;
    g_z[t*64 + k] = mag;
}

// ---------------- k2: per-l sum / sumsq ----------------------------------------
__global__ void k_stats() {
    int bv = blockIdx.x;
    const float* p = g_z + bv*4096;
    int tid = threadIdx.x;
    int l = tid >> 2, seg = (tid & 3)*16;
    const float* q = p + l*64 + seg;
    float s = 0.f, ss = 0.f;
    #pragma unroll
    for (int i = 0; i < 16; i++) { float v = q[i]; s += v; ss += v*v; }
    s  += __shfl_xor_sync(0xffffffffu, s, 1);  ss += __shfl_xor_sync(0xffffffffu, ss, 1);
    s  += __shfl_xor_sync(0xffffffffu, s, 2);  ss += __shfl_xor_sync(0xffffffffu, ss, 2);
    if ((tid & 3) == 0) {
        atomicAdd(&g_sum[l], (double)s);
        atomicAdd(&g_sumsq[l], (double)ss);
    }
}

// ---------------- k3: finalize mean / std (ddof=1) ----------------------------
__global__ void k_statfin() {
    int l = threadIdx.x;
    if (l >= LL) return;
    double n = 32768.0;
    double s = g_sum[l], ss = g_sumsq[l];
    double mean = s / n;
    double var = (ss - s*s/n) / (n - 1.0);
    float sd = (float)sqrt(var);
    g_mean[l] = (float)mean;
    float spe = sd + EPSF;
    g_spe[l] = spe;
    g_sinv[l] = 1.0f / spe;
}

// ---------------- k4: codebook squared norms ----------------------------------
__global__ void k_cbsq(const float* __restrict__ cb) {
    int tid = threadIdx.x;
    int row = blockIdx.x*64 + (tid >> 2);
    const float* p = cb + row*64 + (tid & 3)*16;
    float s = 0.f;
    #pragma unroll
    for (int i = 0; i < 16; i++) { float v = p[i]; s += v*v; }
    s += __shfl_xor_sync(0xffffffffu, s, 1);
    s += __shfl_xor_sync(0xffffffffu, s, 2);
    if ((tid & 3) == 0) g_cbsq[row] = s;
}

// ---------------- k4b: codebook -> tf32 hi/lo mma-fragment layout --------------
// one thread per float4: F = (((q*16+ch)*8+nt)*8+s)*32 + lane
__global__ void k_cbfrag(const float* __restrict__ cb) {
    int F = blockIdx.x*256 + threadIdx.x;
    if (F >= NQ*16*8*8*32) return;
    int lane = F & 31;
    int s    = (F >> 5) & 7;
    int nt   = (F >> 8) & 7;
    int ch   = (F >> 11) & 15;
    int q    = F >> 15;
    int entry = ch*64 + nt*8 + (lane >> 2);
    int kb    = 8*s + (lane & 3);
    const float* src = cb + ((size_t)q*BINS + entry)*64;
    float v0 = src[kb], v1 = src[kb + 4];
    uint32_t h0 = f2tf32(v0); uint32_t l0 = f2tf32(v0 - __uint_as_float(h0));
    uint32_t h1 = f2tf32(v1); uint32_t l1 = f2tf32(v1 - __uint_as_float(h1));
    float4 o;
    o.x = __uint_as_float(h0); o.y = __uint_as_float(h1);
    o.z = __uint_as_float(l0); o.w = __uint_as_float(l1);
    g_cbfrag[F] = o;
}

// ---------------- k5: encoder GEMM + per-(b,e) column norms -------------------
__global__ void __launch_bounds__(256, 2) k_enc(const float* __restrict__ ew,
                                                const float* __restrict__ eb) {
    extern __shared__ float sm[];
    float* zS   = sm;               // 128*TPAD
    float* wS   = zS + 128*TPAD;    // 64*TPAD
    float* red  = wS + 64*TPAD;     // 64*17
    float* meanS= red + 64*17;      // 64
    float* sinvS= meanS + 64;       // 64
    float* ebS  = sinvS + 64;       // 64

    int tid = threadIdx.x;
    int t0 = blockIdx.x * 128;

    if (tid < 64) { meanS[tid] = g_mean[tid]; sinvS[tid] = g_sinv[tid]; ebS[tid] = eb[tid]; }
    {
        const float4* w4 = (const float4*)ew;
        #pragma unroll
        for (int i = 0; i < 4; i++) {
            int f = tid + i*256;
            int e = f >> 4, d4 = f & 15;
            float4 v = w4[f];
            float* dst = wS + e*TPAD + d4*4;
            dst[0]=v.x; dst[1]=v.y; dst[2]=v.z; dst[3]=v.w;
        }
    }
    __syncthreads();
    {
        const float4* z4 = (const float4*)g_z + (size_t)t0*16;
        #pragma unroll
        for (int i = 0; i < 8; i++) {
            int f = tid + i*256;
            int t = f >> 4, d4 = f & 15;
            float4 v = z4[f];
            int l = (t0 + t) & 63;
            float m = meanS[l], si = sinvS[l];
            float* dst = zS + t*TPAD + d4*4;
            dst[0]=(v.x-m)*si; dst[1]=(v.y-m)*si; dst[2]=(v.z-m)*si; dst[3]=(v.w-m)*si;
        }
    }
    __syncthreads();

    int ty = tid >> 4, tx = tid & 15;
    ull acc2[8][4];
    #pragma unroll
    for (int i = 0; i < 8; i++)
        #pragma unroll
        for (int j = 0; j < 4; j++) acc2[i][j] = 0ull;

    #pragma unroll 8
    for (int d = 0; d < 64; d += 2) {
        ull rv[8], cv[4];
        #pragma unroll
        for (int i = 0; i < 8; i++) rv[i] = *(const ull*)(zS + (ty*8+i)*TPAD + d);
        #pragma unroll
        for (int j = 0; j < 4; j++) cv[j] = *(const ull*)(wS + (j*16+tx)*TPAD + d);
        #pragma unroll
        for (int i = 0; i < 8; i++)
            #pragma unroll
            for (int j = 0; j < 4; j++) fma2(acc2[i][j], rv[i], cv[j]);
    }

    float pn[4] = {0.f,0.f,0.f,0.f};
    #pragma unroll
    for (int i = 0; i < 8; i++) {
        int t = t0 + ty*8 + i;
        #pragma unroll
        for (int j = 0; j < 4; j++) {
            int e = j*16 + tx;
            float o = unpack_sum(acc2[i][j]) + ebS[e];
            pn[j] += o*o;
            g_zh[(size_t)t*64 + e] = o;
        }
    }
    #pragma unroll
    for (int j = 0; j < 4; j++) red[(j*16+tx)*17 + ty] = pn[j];
    __syncthreads();
    if (tid < 64) {
        float s = 0.f;
        #pragma unroll
        for (int y = 0; y < 16; y++) s += red[tid*17 + y];
        atomicAdd(&g_colnorm[(t0 >> 10)*64 + tid], (double)s);
    }
}

// ---------------- k6: finalize inverse token-norms ----------------------------
__global__ void k_normfin() {
    int i = blockIdx.x*blockDim.x + threadIdx.x;
    if (i < BB*DD) g_invnorm[i] = 1.0f / sqrtf((float)g_colnorm[i]);
}

// ============================ k7: mma.sync RVQ ================================
// 128 blocks x 512 threads; 256 tokens/block; warp w owns token rows 16w..16w+15
// residual in registers in m16n8k8 A-fragment layout:
//   lane: g=lane>>2, tig=lane&3; rows m0=16w+g, m1=m0+8; k = 8s+tig+4b
// per stage: 16 chunks of 64 entries; B pre-fragmented (g_cbfrag) -> smem memcpy
// 3-pass tf32: AhiBhi + AloBhi + AhiBlo

// smem float offsets
#define F_BF    0                 // 16384 floats (two 8192 buffers, float4-viewed)
#define F_CSQ   16384             // 1024
#define F_QO    17408             // 256*66 = 16896
#define F_INV   34304             // 64
#define F_MEAN  34368             // 64
#define F_SPE   34432             // 64
#define F_DB    34496             // 64
#define F_LOSS  34560             // 16
#define RVQ_SMEMF 34576
#define RVQ_SMEM  (RVQ_SMEMF*4)   // 138304 bytes

__global__ void __launch_bounds__(512) k_rvq(const float* __restrict__ cb,
                                             const float* __restrict__ dw,
                                             const float* __restrict__ db,
                                             float* __restrict__ out) {
    extern __shared__ float sm[];
    float4* bf4  = (float4*)(sm + F_BF);
    float* csqS  = sm + F_CSQ;
    float* qoS   = sm + F_QO;
    float* invS  = sm + F_INV;
    float* meanS = sm + F_MEAN;
    float* speS  = sm + F_SPE;
    float* dbS   = sm + F_DB;
    float* lossW = sm + F_LOSS;

    int tid = threadIdx.x;
    int w = tid >> 5, lane = tid & 31;
    int g = lane >> 2, tig = lane & 3;
    int t0 = blockIdx.x * 256;
    int b  = t0 >> 10;

    if (tid < 64) {
        invS[tid]  = g_invnorm[b*64 + tid];
        meanS[tid] = g_mean[tid];
        speS[tid]  = g_spe[tid];
        dbS[tid]   = db[tid];
    }
    // zero qo
    #pragma unroll
    for (int i = 0; i < 33; i++) {
        int f = tid + i*512;
        if (f < 256*TPAD) qoS[f] = 0.f;
    }
    __syncthreads();

    int m0l = 16*w + g, m1l = m0l + 8;       // local token rows
    int m0g = t0 + m0l, m1g = t0 + m1l;      // global tokens

    // residual registers (A-fragment ownership)
    float R0[8][2], R1[8][2];
    {
        const float* z0 = g_zh + (size_t)m0g*64;
        const float* z1 = g_zh + (size_t)m1g*64;
        #pragma unroll
        for (int s = 0; s < 8; s++)
            #pragma unroll
            for (int b2 = 0; b2 < 2; b2++) {
                int k = 8*s + tig + 4*b2;
                R0[s][b2] = z0[k] * invS[k];
                R1[s][b2] = z1[k] * invS[k];
            }
    }

    for (int q = 0; q < NQ; q++) {
        csqS[tid]       = g_cbsq[q*BINS + tid];
        csqS[tid + 512] = g_cbsq[q*BINS + tid + 512];

        // A hi fragments
        uint32_t AH[8][4];
        #pragma unroll
        for (int s = 0; s < 8; s++) {
            AH[s][0] = f2tf32(R0[s][0]);
            AH[s][1] = f2tf32(R1[s][0]);
            AH[s][2] = f2tf32(R0[s][1]);
            AH[s][3] = f2tf32(R1[s][1]);
        }
        __syncthreads();    // csq visible; prev stage traffic drained

        // prefill chunk 0 into buf0
        {
            const float4* src = g_cbfrag + (size_t)(q*16 + 0)*2048;
            #pragma unroll
            for (int i = 0; i < 4; i++) bf4[tid + i*512] = src[tid + i*512];
        }
        __syncthreads();

        float best0 = INFINITY, best1 = INFINITY;
        int idx0 = 0, idx1 = 0;

        for (int ch = 0; ch < 16; ch++) {
            // fill other buffer for next chunk (concurrent with compute)
            if (ch < 15) {
                const float4* src = g_cbfrag + (size_t)(q*16 + ch + 1)*2048;
                float4* dst = bf4 + ((ch + 1) & 1)*2048;
                #pragma unroll
                for (int i = 0; i < 4; i++) dst[tid + i*512] = src[tid + i*512];
            }
            const float4* buf = bf4 + (ch & 1)*2048;

            float C[8][4];
            #pragma unroll
            for (int nt = 0; nt < 8; nt++)
                #pragma unroll
                for (int j = 0; j < 4; j++) C[nt][j] = 0.f;

            #pragma unroll
            for (int s = 0; s < 8; s++) {
                uint32_t AL[4];
                AL[0] = f2tf32(R0[s][0] - __uint_as_float(AH[s][0]));
                AL[1] = f2tf32(R1[s][0] - __uint_as_float(AH[s][1]));
                AL[2] = f2tf32(R0[s][1] - __uint_as_float(AH[s][2]));
                AL[3] = f2tf32(R1[s][1] - __uint_as_float(AH[s][3]));
                #pragma unroll
                for (int nt = 0; nt < 8; nt++) {
                    float4 bv = buf[(nt*8 + s)*32 + lane];
                    uint32_t bh0 = __float_as_uint(bv.x);
                    uint32_t bh1 = __float_as_uint(bv.y);
                    uint32_t bl0 = __float_as_uint(bv.z);
                    uint32_t bl1 = __float_as_uint(bv.w);
                    mma_tf32(C[nt], AH[s], bh0, bh1);
                    mma_tf32(C[nt], AL,    bh0, bh1);
                    mma_tf32(C[nt], AH[s], bl0, bl1);
                }
            }

            // argmin epilogue: cols 2tig, 2tig+1 of each n-tile
            #pragma unroll
            for (int nt = 0; nt < 8; nt++) {
                int nb = ch*64 + nt*8 + 2*tig;
                float cq0 = csqS[nb], cq1 = csqS[nb + 1];
                float m00 = cq0 - 2.0f*C[nt][0];
                float m01 = cq1 - 2.0f*C[nt][1];
                float m10 = cq0 - 2.0f*C[nt][2];
                float m11 = cq1 - 2.0f*C[nt][3];
                if (m00 < best0) { best0 = m00; idx0 = nb; }
                if (m01 < best0) { best0 = m01; idx0 = nb + 1; }
                if (m10 < best1) { best1 = m10; idx1 = nb; }
                if (m11 < best1) { best1 = m11; idx1 = nb + 1; }
            }
            __syncthreads();
        }

        // cross-lane argmin over the 4 lanes of the column group
        #pragma unroll
        for (int off = 1; off <= 2; off <<= 1) {
            float ov = __shfl_xor_sync(0xffffffffu, best0, off);
            int   oi = __shfl_xor_sync(0xffffffffu, idx0, off);
            if (ov < best0 || (ov == best0 && oi < idx0)) { best0 = ov; idx0 = oi; }
            ov = __shfl_xor_sync(0xffffffffu, best1, off);
            oi = __shfl_xor_sync(0xffffffffu, idx1, off);
            if (ov < best1 || (ov == best1 && oi < idx1)) { best1 = ov; idx1 = oi; }
        }
        if (tig == 0) {
            out[ZQ_OFF + q*NTOK + m0g] = (float)idx0;
            out[ZQ_OFF + q*NTOK + m1g] = (float)idx1;
        }

        // residual & qo update + loss
        float ls = 0.f;
        {
            const float* cr0 = cb + ((size_t)q*BINS + idx0)*64;
            const float* cr1 = cb + ((size_t)q*BINS + idx1)*64;
            #pragma unroll
            for (int s = 0; s < 8; s++)
                #pragma unroll
                for (int b2 = 0; b2 < 2; b2++) {
                    int k = 8*s + tig + 4*b2;
                    float c0v = cr0[k];
                    float nv = R0[s][b2] - c0v; R0[s][b2] = nv; ls += nv*nv;
                    qoS[m0l*TPAD + k] += c0v;
                    float c1v = cr1[k];
                    nv = R1[s][b2] - c1v; R1[s][b2] = nv; ls += nv*nv;
                    qoS[m1l*TPAD + k] += c1v;
                }
        }
        #pragma unroll
        for (int o = 16; o; o >>= 1) ls += __shfl_xor_sync(0xffffffffu, ls, o);
        if (lane == 0) lossW[w] = ls;
        __syncthreads();
        if (tid == 0) {
            float s = 0.f;
            #pragma unroll
            for (int i = 0; i < 16; i++) s += lossW[i];
            atomicAdd(&g_loss[q], (double)s);
        }
        __syncthreads();
    }

    // -------- decoder: out = (qo @ dec_w^T + db) * spe[l] + mean[l] -----------
    {
        float* dwS = sm + F_BF;   // reuse B region
        #pragma unroll
        for (int i = 0; i < 8; i++) {
            int f = tid + i*512;
            int e = f >> 6, k = f & 63;
            dwS[e*TPAD + k] = dw[f];
        }
        __syncthreads();

        int ty = tid >> 4, tx = tid & 15;   // 32 token-groups x 16 e-lanes
        float acc[8][4];
        #pragma unroll
        for (int i = 0; i < 8; i++)
            #pragma unroll
            for (int j = 0; j < 4; j++) acc[i][j] = 0.f;
        #pragma unroll 8
        for (int k = 0; k < 64; k++) {
            float rv[8], cv[4];
            #pragma unroll
            for (int i = 0; i < 8; i++) rv[i] = qoS[(ty*8+i)*TPAD + k];
            #pragma unroll
            for (int j = 0; j < 4; j++) cv[j] = dwS[(j*16+tx)*TPAD + k];
            #pragma unroll
            for (int i = 0; i < 8; i++)
                #pragma unroll
                for (int j = 0; j < 4; j++) acc[i][j] += rv[i]*cv[j];
        }
        #pragma unroll
        for (int i = 0; i < 8; i++) {
            int t = t0 + ty*8 + i;
            int l = t & 63;
            float sp = speS[l], mm = meanS[l];
            #pragma unroll
            for (int j = 0; j < 4; j++) {
                int e = j*16 + tx;
                out[(size_t)t*64 + e] = (acc[i][j] + dbS[e])*sp + mm;
            }
        }
    }
}

// ---------------- k8: commit loss ---------------------------------------------
__global__ void k_lossfin(float* __restrict__ out) {
    if (threadIdx.x == 0 && blockIdx.x == 0) {
        double s = 0.0;
        for (int q = 0; q < NQ; q++) s += g_loss[q] / (double)(NTOK*DD);
        out[ZQ_OFF + CODES_N] = (float)(s / (double)NQ);
    }
}

// ---------------- launch ------------------------------------------------------
extern "C" void kernel_launch(void* const* d_in, const int* in_sizes, int n_in,
                              void* d_out, int out_size) {
    const float* x    = (const float*)d_in[0];
    const float* ew   = (const float*)d_in[1];
    const float* eb   = (const float*)d_in[2];
    const float* dwp  = (const float*)d_in[3];
    const float* dbp  = (const float*)d_in[4];
    const float* cb   = (const float*)d_in[5];
    float* out = (float*)d_out;

    const int ENC_SMEM = (128*TPAD + 64*TPAD + 64*17 + 3*64) * 4;
    cudaFuncSetAttribute(k_enc, cudaFuncAttributeMaxDynamicSharedMemorySize, ENC_SMEM);
    cudaFuncSetAttribute(k_rvq, cudaFuncAttributeMaxDynamicSharedMemorySize, RVQ_SMEM);

    k_zero<<<1, 256>>>();
    k_fft<<<BB*LL, 1024>>>(x);
    k_stats<<<512, 256>>>();
    k_statfin<<<1, 64>>>();
    k_cbsq<<<128, 256>>>(cb);
    k_cbfrag<<<(NQ*16*8*8*32 + 255)/256, 256>>>(cb);
    k_enc<<<256, 256, ENC_SMEM>>>(ew, eb);
    k_normfin<<<8, 256>>>();
    k_rvq<<<128, 512, RVQ_SMEM>>>(cb, dwp, dbp, out);
    k_lossfin<<<1, 32>>>(out);
}

// round 7
// speedup vs baseline: 2.4245x; 1.6177x over previous
#include <cuda_runtime.h>
#include <cuda_fp16.h>
#include <math.h>
#include <stdint.h>

#define BB 32
#define VV 16
#define LL 64
#define PP 64
#define DD 64
#define NTOK 32768      // BB*VV*LL
#define NQ 8
#define BINS 1024
#define EPSF 1e-5f
#define TPAD 66

#define ZQ_OFF   (NTOK*DD)           // 2097152
#define CODES_N  (NQ*NTOK)           // 262144

typedef unsigned long long ull;

// m16n8k16 f16 mma, fp32 accum (sm_80+; legal under compute_100)
__device__ __forceinline__ void mma_f16(float* c, const uint32_t* a,
                                        uint32_t b0, uint32_t b1) {
    asm volatile("mma.sync.aligned.m16n8k16.row.col.f32.f16.f16.f32 "
        "{%0,%1,%2,%3}, {%4,%5,%6,%7}, {%8,%9}, {%0,%1,%2,%3};"
        : "+f"(c[0]), "+f"(c[1]), "+f"(c[2]), "+f"(c[3])
        : "r"(a[0]), "r"(a[1]), "r"(a[2]), "r"(a[3]), "r"(b0), "r"(b1));
}

__device__ __forceinline__ uint32_t pack_h2(float x, float y) {
    __half2 h = __floats2half2_rn(x, y);
    return *reinterpret_cast<uint32_t*>(&h);
}

// fp32x2 helpers for k_enc (lowered to 2x FFMA on sm_100; harmless)
__device__ __forceinline__ void fma2(ull& acc, ull a, ull b) {
    asm("fma.rn.f32x2 %0, %1, %2, %0;" : "+l"(acc) : "l"(a), "l"(b));
}
__device__ __forceinline__ float unpack_sum(ull a) {
    float2 p = *reinterpret_cast<float2*>(&a);
    return p.x + p.y;
}

// ---------------- scratch (device globals; no allocation allowed) -------------
__device__ __align__(16) float  g_z[NTOK*DD];
__device__ __align__(16) float  g_zh[NTOK*DD];
// fp16 hi/lo fragment codebook: F = (((q*16+ch)*8+nt)*4+s)*32+lane
// uint4 = {bhi0, bhi1, blo0, blo1}
__device__ __align__(16) uint4  g_cbf16[NQ*16*8*4*32];
__device__ float  g_cbsq[NQ*BINS];
__device__ double g_sum[LL], g_sumsq[LL];
__device__ float  g_mean[LL], g_sinv[LL], g_spe[LL];
__device__ double g_colnorm[BB*DD];
__device__ float  g_invnorm[BB*DD];
__device__ double g_loss[NQ];

// ---------------- k0: zero accumulators ---------------------------------------
__global__ void k_zero() {
    int t = threadIdx.x;
    if (t < LL) { g_sum[t] = 0.0; g_sumsq[t] = 0.0; }
    if (t < NQ) g_loss[t] = 0.0;
    for (int i = t; i < BB*DD; i += blockDim.x) g_colnorm[i] = 0.0;
}

// ---------------- k1: 64-pt DFT magnitude per patch ---------------------------
__global__ void __launch_bounds__(1024) k_fft(const float* __restrict__ x) {
    __shared__ float xs[PP*VV];
    __shared__ float ct[64], st[64];
    int bi = blockIdx.x;
    int b = bi >> 6, l = bi & 63;
    int tid = threadIdx.x;
    xs[tid] = x[(size_t)(b*4096 + l*64)*16 + tid];
    if (tid < 64) { float a = (float)tid * (1.0f/32.0f); ct[tid] = cospif(a); st[tid] = sinpif(a); }
    __syncthreads();
    int v = tid >> 6, k = tid & 63;
    float re = 0.f, im = 0.f;
    #pragma unroll 16
    for (int j = 0; j < 64; j++) {
        float val = xs[j*16 + v];
        int a = (j*k) & 63;
        re += val * ct[a];
        im += val * st[a];
    }
    float mag = sqrtf(re*re + im*im);
    int t = (b*VV + v)*LL + l;
    g_z[t*64 + k] = mag;
}

// ---------------- k2: per-l sum / sumsq ----------------------------------------
__global__ void k_stats() {
    int bv = blockIdx.x;
    const float* p = g_z + bv*4096;
    int tid = threadIdx.x;
    int l = tid >> 2, seg = (tid & 3)*16;
    const float* q = p + l*64 + seg;
    float s = 0.f, ss = 0.f;
    #pragma unroll
    for (int i = 0; i < 16; i++) { float v = q[i]; s += v; ss += v*v; }
    s  += __shfl_xor_sync(0xffffffffu, s, 1);  ss += __shfl_xor_sync(0xffffffffu, ss, 1);
    s  += __shfl_xor_sync(0xffffffffu, s, 2);  ss += __shfl_xor_sync(0xffffffffu, ss, 2);
    if ((tid & 3) == 0) {
        atomicAdd(&g_sum[l], (double)s);
        atomicAdd(&g_sumsq[l], (double)ss);
    }
}

// ---------------- k3: finalize mean / std (ddof=1) ----------------------------
__global__ void k_statfin() {
    int l = threadIdx.x;
    if (l >= LL) return;
    double n = 32768.0;
    double s = g_sum[l], ss = g_sumsq[l];
    double mean = s / n;
    double var = (ss - s*s/n) / (n - 1.0);
    float sd = (float)sqrt(var);
    g_mean[l] = (float)mean;
    float spe = sd + EPSF;
    g_spe[l] = spe;
    g_sinv[l] = 1.0f / spe;
}

// ---------------- k4: codebook squared norms ----------------------------------
__global__ void k_cbsq(const float* __restrict__ cb) {
    int tid = threadIdx.x;
    int row = blockIdx.x*64 + (tid >> 2);
    const float* p = cb + row*64 + (tid & 3)*16;
    float s = 0.f;
    #pragma unroll
    for (int i = 0; i < 16; i++) { float v = p[i]; s += v*v; }
    s += __shfl_xor_sync(0xffffffffu, s, 1);
    s += __shfl_xor_sync(0xffffffffu, s, 2);
    if ((tid & 3) == 0) g_cbsq[row] = s;
}

// ---------------- k4b: codebook -> fp16 hi/lo mma fragments --------------------
__global__ void k_cbfrag(const float* __restrict__ cb) {
    int F = blockIdx.x*256 + threadIdx.x;
    if (F >= NQ*16*8*4*32) return;
    int lane = F & 31;
    int s    = (F >> 5) & 3;
    int nt   = (F >> 7) & 7;
    int ch   = (F >> 10) & 15;
    int q    = F >> 14;
    int g    = lane >> 2, tig = lane & 3;
    int entry = ch*64 + nt*8 + g;
    int k0 = 16*s + 2*tig;
    const float* src = cb + ((size_t)q*BINS + entry)*64;
    float v0 = src[k0],     v1 = src[k0+1];
    float v2 = src[k0+8],   v3 = src[k0+9];
    float h0 = __half2float(__float2half_rn(v0));
    float h1 = __half2float(__float2half_rn(v1));
    float h2 = __half2float(__float2half_rn(v2));
    float h3 = __half2float(__float2half_rn(v3));
    uint4 o;
    o.x = pack_h2(h0, h1);
    o.y = pack_h2(h2, h3);
    o.z = pack_h2(v0 - h0, v1 - h1);
    o.w = pack_h2(v2 - h2, v3 - h3);
    g_cbf16[F] = o;
}

// ---------------- k5: encoder GEMM + per-(b,e) column norms -------------------
__global__ void __launch_bounds__(256, 2) k_enc(const float* __restrict__ ew,
                                                const float* __restrict__ eb) {
    extern __shared__ float sm[];
    float* zS   = sm;               // 128*TPAD
    float* wS   = zS + 128*TPAD;    // 64*TPAD
    float* red  = wS + 64*TPAD;     // 64*17
    float* meanS= red + 64*17;      // 64
    float* sinvS= meanS + 64;       // 64
    float* ebS  = sinvS + 64;       // 64

    int tid = threadIdx.x;
    int t0 = blockIdx.x * 128;

    if (tid < 64) { meanS[tid] = g_mean[tid]; sinvS[tid] = g_sinv[tid]; ebS[tid] = eb[tid]; }
    {
        const float4* w4 = (const float4*)ew;
        #pragma unroll
        for (int i = 0; i < 4; i++) {
            int f = tid + i*256;
            int e = f >> 4, d4 = f & 15;
            float4 v = w4[f];
            float* dst = wS + e*TPAD + d4*4;
            dst[0]=v.x; dst[1]=v.y; dst[2]=v.z; dst[3]=v.w;
        }
    }
    __syncthreads();
    {
        const float4* z4 = (const float4*)g_z + (size_t)t0*16;
        #pragma unroll
        for (int i = 0; i < 8; i++) {
            int f = tid + i*256;
            int t = f >> 4, d4 = f & 15;
            float4 v = z4[f];
            int l = (t0 + t) & 63;
            float m = meanS[l], si = sinvS[l];
            float* dst = zS + t*TPAD + d4*4;
            dst[0]=(v.x-m)*si; dst[1]=(v.y-m)*si; dst[2]=(v.z-m)*si; dst[3]=(v.w-m)*si;
        }
    }
    __syncthreads();

    int ty = tid >> 4, tx = tid & 15;
    ull acc2[8][4];
    #pragma unroll
    for (int i = 0; i < 8; i++)
        #pragma unroll
        for (int j = 0; j < 4; j++) acc2[i][j] = 0ull;

    #pragma unroll 8
    for (int d = 0; d < 64; d += 2) {
        ull rv[8], cv[4];
        #pragma unroll
        for (int i = 0; i < 8; i++) rv[i] = *(const ull*)(zS + (ty*8+i)*TPAD + d);
        #pragma unroll
        for (int j = 0; j < 4; j++) cv[j] = *(const ull*)(wS + (j*16+tx)*TPAD + d);
        #pragma unroll
        for (int i = 0; i < 8; i++)
            #pragma unroll
            for (int j = 0; j < 4; j++) fma2(acc2[i][j], rv[i], cv[j]);
    }

    float pn[4] = {0.f,0.f,0.f,0.f};
    #pragma unroll
    for (int i = 0; i < 8; i++) {
        int t = t0 + ty*8 + i;
        #pragma unroll
        for (int j = 0; j < 4; j++) {
            int e = j*16 + tx;
            float o = unpack_sum(acc2[i][j]) + ebS[e];
            pn[j] += o*o;
            g_zh[(size_t)t*64 + e] = o;
        }
    }
    #pragma unroll
    for (int j = 0; j < 4; j++) red[(j*16+tx)*17 + ty] = pn[j];
    __syncthreads();
    if (tid < 64) {
        float s = 0.f;
        #pragma unroll
        for (int y = 0; y < 16; y++) s += red[tid*17 + y];
        atomicAdd(&g_colnorm[(t0 >> 10)*64 + tid], (double)s);
    }
}

// ---------------- k6: finalize inverse token-norms ----------------------------
__global__ void k_normfin() {
    int i = blockIdx.x*blockDim.x + threadIdx.x;
    if (i < BB*DD) g_invnorm[i] = 1.0f / sqrtf((float)g_colnorm[i]);
}

// ============================ k7: fp16x3 mma RVQ ===============================
// 128 blocks x 512 threads (16 warps); warp w owns token rows 16w..16w+15.
// Residual in registers (m16n8k16 A-fragment layout). QO = R_init - R_final,
// recomputed at decode time (no QO registers).
// Per stage: 16 chunks of 64 entries; per chunk per warp: 4 ksteps x 8 ntiles,
// 1 LDS.128 (hi+lo packed) + 3 mma each.

// smem float offsets (overlay: stage view / decode view)
#define F_BF    0                  // 8192 floats = 2048 uint4 (two chunk buffers)
#define F_CSQ   8448               // 1024 (starts past decode-qo region)
#define F_QO    0                  // decode: 256*66 = 16896
#define F_DW    16896              // decode: 64*66 = 4224
#define F_FIX   21120
#define F_INV   (F_FIX)
#define F_MEAN  (F_FIX+64)
#define F_SPE   (F_FIX+128)
#define F_DB    (F_FIX+192)
#define F_LOSS  (F_FIX+256)        // 16
#define RVQ_SMEMF (F_FIX+272)
#define RVQ_SMEM  (RVQ_SMEMF*4)

__global__ void __launch_bounds__(512) k_rvq(const float* __restrict__ cb,
                                             const float* __restrict__ dw,
                                             const float* __restrict__ db,
                                             float* __restrict__ out) {
    extern __shared__ float sm[];
    uint4* bf4   = (uint4*)(sm + F_BF);
    float* csqS  = sm + F_CSQ;
    float* invS  = sm + F_INV;
    float* meanS = sm + F_MEAN;
    float* speS  = sm + F_SPE;
    float* dbS   = sm + F_DB;
    float* lossW = sm + F_LOSS;

    int tid = threadIdx.x;
    int w = tid >> 5, lane = tid & 31;
    int g = lane >> 2, tig = lane & 3;
    int t0 = blockIdx.x * 256;
    int b  = t0 >> 10;

    if (tid < 64) {
        invS[tid]  = g_invnorm[b*64 + tid];
        meanS[tid] = g_mean[tid];
        speS[tid]  = g_spe[tid];
        dbS[tid]   = db[tid];
    }
    __syncthreads();

    int m0l = 16*w + g, m1l = m0l + 8;
    int m0g = t0 + m0l, m1g = t0 + m1l;

    // residual registers in A-fragment layout:
    // R[s*4+j]: k = 16s + 2tig + (j&1) + 8*(j>>1)
    float R0[16], R1[16];
    {
        const float* z0 = g_zh + (size_t)m0g*64;
        const float* z1 = g_zh + (size_t)m1g*64;
        #pragma unroll
        for (int s = 0; s < 4; s++) {
            int ka = 16*s + 2*tig;
            float2 a0 = *(const float2*)(z0 + ka);
            float2 b0 = *(const float2*)(z0 + ka + 8);
            float2 a1 = *(const float2*)(z1 + ka);
            float2 b1 = *(const float2*)(z1 + ka + 8);
            R0[s*4+0] = a0.x * invS[ka];     R0[s*4+1] = a0.y * invS[ka+1];
            R0[s*4+2] = b0.x * invS[ka+8];   R0[s*4+3] = b0.y * invS[ka+9];
            R1[s*4+0] = a1.x * invS[ka];     R1[s*4+1] = a1.y * invS[ka+1];
            R1[s*4+2] = b1.x * invS[ka+8];   R1[s*4+3] = b1.y * invS[ka+9];
        }
    }

    for (int q = 0; q < NQ; q++) {
        // A hi/lo fragments for this stage
        uint32_t AH[4][4], AL[4][4];
        #pragma unroll
        for (int s = 0; s < 4; s++) {
            float h00 = __half2float(__float2half_rn(R0[s*4+0]));
            float h01 = __half2float(__float2half_rn(R0[s*4+1]));
            float h02 = __half2float(__float2half_rn(R0[s*4+2]));
            float h03 = __half2float(__float2half_rn(R0[s*4+3]));
            float h10 = __half2float(__float2half_rn(R1[s*4+0]));
            float h11 = __half2float(__float2half_rn(R1[s*4+1]));
            float h12 = __half2float(__float2half_rn(R1[s*4+2]));
            float h13 = __half2float(__float2half_rn(R1[s*4+3]));
            AH[s][0] = pack_h2(h00, h01);
            AH[s][1] = pack_h2(h10, h11);
            AH[s][2] = pack_h2(h02, h03);
            AH[s][3] = pack_h2(h12, h13);
            AL[s][0] = pack_h2(R0[s*4+0]-h00, R0[s*4+1]-h01);
            AL[s][1] = pack_h2(R1[s*4+0]-h10, R1[s*4+1]-h11);
            AL[s][2] = pack_h2(R0[s*4+2]-h02, R0[s*4+3]-h03);
            AL[s][3] = pack_h2(R1[s*4+2]-h12, R1[s*4+3]-h13);
        }

        __syncthreads();   // previous-iteration smem consumers done
        csqS[tid]       = g_cbsq[q*BINS + tid];
        csqS[tid + 512] = g_cbsq[q*BINS + tid + 512];
        // prefill chunk 0 into buf 0 (1024 uint4 / 512 threads)
        {
            const uint4* src = g_cbf16 + (size_t)(q*16 + 0)*1024;
            bf4[tid]       = src[tid];
            bf4[tid + 512] = src[tid + 512];
        }
        __syncthreads();

        float best0 = INFINITY, best1 = INFINITY;
        int idx0 = 0, idx1 = 0;

        for (int ch = 0; ch < 16; ch++) {
            if (ch < 15) {   // prefetch next chunk into other buffer
                const uint4* src = g_cbf16 + (size_t)(q*16 + ch + 1)*1024;
                uint4* dst = bf4 + ((ch + 1) & 1)*1024;
                dst[tid]       = src[tid];
                dst[tid + 512] = src[tid + 512];
            }
            const uint4* buf = bf4 + (ch & 1)*1024;

            float C[8][4];
            #pragma unroll
            for (int nt = 0; nt < 8; nt++)
                #pragma unroll
                for (int j = 0; j < 4; j++) C[nt][j] = 0.f;

            #pragma unroll
            for (int s = 0; s < 4; s++) {
                #pragma unroll
                for (int nt = 0; nt < 8; nt++) {
                    uint4 bv = buf[(nt*4 + s)*32 + lane];
                    mma_f16(C[nt], AH[s], bv.x, bv.y);   // hi*hi
                    mma_f16(C[nt], AL[s], bv.x, bv.y);   // lo*hi
                    mma_f16(C[nt], AH[s], bv.z, bv.w);   // hi*lo
                }
            }

            // argmin epilogue: C cols 2tig, 2tig+1
            #pragma unroll
            for (int nt = 0; nt < 8; nt++) {
                int nb = ch*64 + nt*8 + 2*tig;
                float cq0 = csqS[nb], cq1 = csqS[nb + 1];
                float m00 = cq0 - 2.0f*C[nt][0];
                float m01 = cq1 - 2.0f*C[nt][1];
                float m10 = cq0 - 2.0f*C[nt][2];
                float m11 = cq1 - 2.0f*C[nt][3];
                if (m00 < best0) { best0 = m00; idx0 = nb; }
                if (m01 < best0) { best0 = m01; idx0 = nb + 1; }
                if (m10 < best1) { best1 = m10; idx1 = nb; }
                if (m11 < best1) { best1 = m11; idx1 = nb + 1; }
            }
            __syncthreads();   // all warps done with buf[ch&1] before refill
        }

        // cross-lane argmin over the 4 lanes of the column group
        #pragma unroll
        for (int off = 1; off <= 2; off <<= 1) {
            float ov = __shfl_xor_sync(0xffffffffu, best0, off);
            int   oi = __shfl_xor_sync(0xffffffffu, idx0, off);
            if (ov < best0 || (ov == best0 && oi < idx0)) { best0 = ov; idx0 = oi; }
            ov = __shfl_xor_sync(0xffffffffu, best1, off);
            oi = __shfl_xor_sync(0xffffffffu, idx1, off);
            if (ov < best1 || (ov == best1 && oi < idx1)) { best1 = ov; idx1 = oi; }
        }
        if (tig == 0) {
            out[ZQ_OFF + q*NTOK + m0g] = (float)idx0;
            out[ZQ_OFF + q*NTOK + m1g] = (float)idx1;
        }

        // residual update + loss
        float ls = 0.f;
        {
            const float* cr0 = cb + ((size_t)q*BINS + idx0)*64;
            const float* cr1 = cb + ((size_t)q*BINS + idx1)*64;
            #pragma unroll
            for (int s = 0; s < 4; s++) {
                int ka = 16*s + 2*tig;
                float2 c0a = *(const float2*)(cr0 + ka);
                float2 c0b = *(const float2*)(cr0 + ka + 8);
                float2 c1a = *(const float2*)(cr1 + ka);
                float2 c1b = *(const float2*)(cr1 + ka + 8);
                float nv;
                nv = R0[s*4+0]-c0a.x; R0[s*4+0]=nv; ls += nv*nv;
                nv = R0[s*4+1]-c0a.y; R0[s*4+1]=nv; ls += nv*nv;
                nv = R0[s*4+2]-c0b.x; R0[s*4+2]=nv; ls += nv*nv;
                nv = R0[s*4+3]-c0b.y; R0[s*4+3]=nv; ls += nv*nv;
                nv = R1[s*4+0]-c1a.x; R1[s*4+0]=nv; ls += nv*nv;
                nv = R1[s*4+1]-c1a.y; R1[s*4+1]=nv; ls += nv*nv;
                nv = R1[s*4+2]-c1b.x; R1[s*4+2]=nv; ls += nv*nv;
                nv = R1[s*4+3]-c1b.y; R1[s*4+3]=nv; ls += nv*nv;
            }
        }
        #pragma unroll
        for (int o = 16; o; o >>= 1) ls += __shfl_xor_sync(0xffffffffu, ls, o);
        if (lane == 0) lossW[w] = ls;
        __syncthreads();
        if (tid == 0) {
            float s = 0.f;
            #pragma unroll
            for (int i = 0; i < 16; i++) s += lossW[i];
            atomicAdd(&g_loss[q], (double)s);
        }
        __syncthreads();
    }

    // -------- decode: QO = R_init - R_final; out = (QO @ dw^T + db)*spe + mean
    {
        float* qoS = sm + F_QO;
        // scatter QO fragments to smem (recompute R_init from g_zh)
        const float* z0 = g_zh + (size_t)m0g*64;
        const float* z1 = g_zh + (size_t)m1g*64;
        #pragma unroll
        for (int s = 0; s < 4; s++) {
            int ka = 16*s + 2*tig;
            float2 a0 = *(const float2*)(z0 + ka);
            float2 b0 = *(const float2*)(z0 + ka + 8);
            float2 a1 = *(const float2*)(z1 + ka);
            float2 b1 = *(const float2*)(z1 + ka + 8);
            qoS[m0l*TPAD + ka]     = a0.x*invS[ka]   - R0[s*4+0];
            qoS[m0l*TPAD + ka + 1] = a0.y*invS[ka+1] - R0[s*4+1];
            qoS[m0l*TPAD + ka + 8] = b0.x*invS[ka+8] - R0[s*4+2];
            qoS[m0l*TPAD + ka + 9] = b0.y*invS[ka+9] - R0[s*4+3];
            qoS[m1l*TPAD + ka]     = a1.x*invS[ka]   - R1[s*4+0];
            qoS[m1l*TPAD + ka + 1] = a1.y*invS[ka+1] - R1[s*4+1];
            qoS[m1l*TPAD + ka + 8] = b1.x*invS[ka+8] - R1[s*4+2];
            qoS[m1l*TPAD + ka + 9] = b1.y*invS[ka+9] - R1[s*4+3];
        }
        float* dwS = sm + F_DW;
        #pragma unroll
        for (int i = 0; i < 8; i++) {
            int f = tid + i*512;
            int e = f >> 6, k = f & 63;
            dwS[e*TPAD + k] = dw[f];
        }
        __syncthreads();

        int ty = tid >> 4, tx = tid & 15;   // 32 token-groups x 16 e-lanes
        float acc[8][4];
        #pragma unroll
        for (int i = 0; i < 8; i++)
            #pragma unroll
            for (int j = 0; j < 4; j++) acc[i][j] = 0.f;
        #pragma unroll 8
        for (int k = 0; k < 64; k++) {
            float rv[8], cv[4];
            #pragma unroll
            for (int i = 0; i < 8; i++) rv[i] = qoS[(ty*8+i)*TPAD + k];
            #pragma unroll
            for (int j = 0; j < 4; j++) cv[j] = dwS[(j*16+tx)*TPAD + k];
            #pragma unroll
            for (int i = 0; i < 8; i++)
                #pragma unroll
                for (int j = 0; j < 4; j++) acc[i][j] += rv[i]*cv[j];
        }
        #pragma unroll
        for (int i = 0; i < 8; i++) {
            int t = t0 + ty*8 + i;
            int l = t & 63;
            float sp = speS[l], mm = meanS[l];
            #pragma unroll
            for (int j = 0; j < 4; j++) {
                int e = j*16 + tx;
                out[(size_t)t*64 + e] = (acc[i][j] + dbS[e])*sp + mm;
            }
        }
    }
}

// ---------------- k8: commit loss ---------------------------------------------
__global__ void k_lossfin(float* __restrict__ out) {
    if (threadIdx.x == 0 && blockIdx.x == 0) {
        double s = 0.0;
        for (int q = 0; q < NQ; q++) s += g_loss[q] / (double)(NTOK*DD);
        out[ZQ_OFF + CODES_N] = (float)(s / (double)NQ);
    }
}

// ---------------- launch ------------------------------------------------------
extern "C" void kernel_launch(void* const* d_in, const int* in_sizes, int n_in,
                              void* d_out, int out_size) {
    const float* x    = (const float*)d_in[0];
    const float* ew   = (const float*)d_in[1];
    const float* eb   = (const float*)d_in[2];
    const float* dwp  = (const float*)d_in[3];
    const float* dbp  = (const float*)d_in[4];
    const float* cb   = (const float*)d_in[5];
    float* out = (float*)d_out;

    const int ENC_SMEM = (128*TPAD + 64*TPAD + 64*17 + 3*64) * 4;
    cudaFuncSetAttribute(k_enc, cudaFuncAttributeMaxDynamicSharedMemorySize, ENC_SMEM);
    cudaFuncSetAttribute(k_rvq, cudaFuncAttributeMaxDynamicSharedMemorySize, RVQ_SMEM);

    k_zero<<<1, 256>>>();
    k_fft<<<BB*LL, 1024>>>(x);
    k_stats<<<512, 256>>>();
    k_statfin<<<1, 64>>>();
    k_cbsq<<<128, 256>>>(cb);
    k_cbfrag<<<(NQ*16*8*4*32 + 255)/256, 256>>>(cb);
    k_enc<<<256, 256, ENC_SMEM>>>(ew, eb);
    k_normfin<<<8, 256>>>();
    k_rvq<<<128, 512, RVQ_SMEM>>>(cb, dwp, dbp, out);
    k_lossfin<<<1, 32>>>(out);
}